// round 13
// baseline (speedup 1.0000x reference)
#include <cuda_runtime.h>
#include <cstdint>

// Problem constants (fixed by the dataset)
#define NN 500000
#define GG 1000

// ---------------------------------------------------------------------------
// Node struct: deg (u64: lo32=deg_in, hi32=deg_out) + agg1, 16B for LDG.128.
// One memset zeroes both fields. t is computed inline in scatter2 (k_t gone).
// ---------------------------------------------------------------------------
struct __align__(16) Node {
    unsigned long long deg;
    float              agg1;
    float              pad;
};

__device__ Node  g_node[NN];   // 8 MB, single memset
__device__ float g_A   [NN];   // layer-2 scalar aggregation
__device__ float g_S   [GG];   // pooled scalar sum per graph
__device__ float g_cnt [GG];   // nodes per graph

#define ONE_IN  1ull
#define ONE_OUT (1ull << 32)

__device__ __forceinline__ void red_f32(float* p, float v) {
    asm volatile("red.global.add.f32 [%0], %1;" :: "l"(p), "f"(v) : "memory");
}
__device__ __forceinline__ void red_u64(unsigned long long* p, unsigned long long v) {
    asm volatile("red.global.add.u64 [%0], %1;" :: "l"(p), "l"(v) : "memory");
}

// ---------------------------------------------------------------------------
// K1: degree histogram into node.deg. 8 edges / thread, flat grid.
//     Pre-sync: index loads (inputs) + zero S/cnt (untouched upstream).
// ---------------------------------------------------------------------------
__global__ void k_deg(const int* __restrict__ src, const int* __restrict__ dst, int E) {
    int i = blockIdx.x * blockDim.x + threadIdx.x;
    if (i < GG) { g_S[i] = 0.0f; g_cnt[i] = 0.0f; }   // untouched until k_pool
    int base = i << 3;
    if (base + 7 < E) {
        int4 s0 = *reinterpret_cast<const int4*>(src + base);
        int4 s1 = *reinterpret_cast<const int4*>(src + base + 4);
        int4 d0 = *reinterpret_cast<const int4*>(dst + base);
        int4 d1 = *reinterpret_cast<const int4*>(dst + base + 4);
        cudaGridDependencySynchronize();   // wait: g_node memset visible
        red_u64(&g_node[s0.x].deg, ONE_OUT); red_u64(&g_node[s0.y].deg, ONE_OUT);
        red_u64(&g_node[s0.z].deg, ONE_OUT); red_u64(&g_node[s0.w].deg, ONE_OUT);
        red_u64(&g_node[s1.x].deg, ONE_OUT); red_u64(&g_node[s1.y].deg, ONE_OUT);
        red_u64(&g_node[s1.z].deg, ONE_OUT); red_u64(&g_node[s1.w].deg, ONE_OUT);
        red_u64(&g_node[d0.x].deg, ONE_IN);  red_u64(&g_node[d0.y].deg, ONE_IN);
        red_u64(&g_node[d0.z].deg, ONE_IN);  red_u64(&g_node[d0.w].deg, ONE_IN);
        red_u64(&g_node[d1.x].deg, ONE_IN);  red_u64(&g_node[d1.y].deg, ONE_IN);
        red_u64(&g_node[d1.z].deg, ONE_IN);  red_u64(&g_node[d1.w].deg, ONE_IN);
    } else {
        cudaGridDependencySynchronize();
        for (int e = base; e < E; ++e) {
            red_u64(&g_node[src[e]].deg, ONE_OUT);
            red_u64(&g_node[dst[e]].deg, ONE_IN);
        }
    }
}

// ---------------------------------------------------------------------------
// K2: layer-1 scatter, x0 inline. 8 edges / thread.
//     Pre-sync: index loads + zero g_A (untouched upstream; must complete
//     before scatter2, which PDL-waits on this whole kernel).
// ---------------------------------------------------------------------------
__device__ __forceinline__ float x0_of(unsigned long long p) {
    float di = (float)(unsigned)p;
    float dq = (float)(unsigned)(p >> 32);
    return di * rsqrtf(fmaxf(dq, 1.0f));
}

__global__ void k_scatter1(const int* __restrict__ src, const int* __restrict__ dst,
                           int E, int N) {
    int i = blockIdx.x * blockDim.x + threadIdx.x;
    int zb = i << 2;                        // zero A: first ceil(N/4) threads
    if (zb < N) {
        if (zb + 3 < N) {
            *reinterpret_cast<float4*>(g_A + zb) = make_float4(0.f, 0.f, 0.f, 0.f);
        } else {
            for (int n = zb; n < N; ++n) g_A[n] = 0.0f;
        }
    }
    int base = i << 3;
    if (base + 7 < E) {
        int4 s0 = *reinterpret_cast<const int4*>(src + base);
        int4 s1 = *reinterpret_cast<const int4*>(src + base + 4);
        int4 d0 = *reinterpret_cast<const int4*>(dst + base);
        int4 d1 = *reinterpret_cast<const int4*>(dst + base + 4);
        cudaGridDependencySynchronize();   // wait: k_deg complete
        float v0 = x0_of(__ldg(&g_node[s0.x].deg));
        float v1 = x0_of(__ldg(&g_node[s0.y].deg));
        float v2 = x0_of(__ldg(&g_node[s0.z].deg));
        float v3 = x0_of(__ldg(&g_node[s0.w].deg));
        float v4 = x0_of(__ldg(&g_node[s1.x].deg));
        float v5 = x0_of(__ldg(&g_node[s1.y].deg));
        float v6 = x0_of(__ldg(&g_node[s1.z].deg));
        float v7 = x0_of(__ldg(&g_node[s1.w].deg));
        red_f32(&g_node[d0.x].agg1, v0); red_f32(&g_node[d0.y].agg1, v1);
        red_f32(&g_node[d0.z].agg1, v2); red_f32(&g_node[d0.w].agg1, v3);
        red_f32(&g_node[d1.x].agg1, v4); red_f32(&g_node[d1.y].agg1, v5);
        red_f32(&g_node[d1.z].agg1, v6); red_f32(&g_node[d1.w].agg1, v7);
    } else {
        cudaGridDependencySynchronize();
        for (int e = base; e < E; ++e)
            red_f32(&g_node[dst[e]].agg1, x0_of(__ldg(&g_node[src[e]].deg)));
    }
}

// ---------------------------------------------------------------------------
// K3: layer-2 scatter with inline t.  A[dst] += agg1[src]*isi[src]*iso[src].
//     4 edges / thread (16B struct gather = 1 lane, same as 4B; keeps regs low).
// ---------------------------------------------------------------------------
__device__ __forceinline__ float t_of(float4 n) {
    // n = raw 16B of Node: x=deg_in bits, y=deg_out bits, z=agg1, w=pad
    float di = (float)__float_as_uint(n.x);
    float dq = (float)__float_as_uint(n.y);
    return n.z * rsqrtf(fmaxf(di, 1.0f)) * rsqrtf(fmaxf(dq, 1.0f));
}

__global__ void k_scatter2(const int* __restrict__ src, const int* __restrict__ dst, int E) {
    int i = blockIdx.x * blockDim.x + threadIdx.x;
    int base = i << 2;
    const float4* nodes = reinterpret_cast<const float4*>(g_node);
    if (base + 3 < E) {
        int4 s = *reinterpret_cast<const int4*>(src + base);
        int4 d = *reinterpret_cast<const int4*>(dst + base);
        cudaGridDependencySynchronize();   // wait: k_scatter1 complete (agg1, A=0)
        float4 n0 = __ldg(&nodes[s.x]);
        float4 n1 = __ldg(&nodes[s.y]);
        float4 n2 = __ldg(&nodes[s.z]);
        float4 n3 = __ldg(&nodes[s.w]);
        red_f32(&g_A[d.x], t_of(n0));
        red_f32(&g_A[d.y], t_of(n1));
        red_f32(&g_A[d.z], t_of(n2));
        red_f32(&g_A[d.w], t_of(n3));
    } else {
        cudaGridDependencySynchronize();
        for (int e = base; e < E; ++e)
            red_f32(&g_A[dst[e]], t_of(__ldg(&nodes[src[e]])));
    }
}

// ---------------------------------------------------------------------------
// K4: pooling. gid load (input) before sync; node/A reads + REDs after.
// ---------------------------------------------------------------------------
__global__ void k_pool(const int* __restrict__ gid, int N) {
    int i = blockIdx.x * blockDim.x + threadIdx.x;
    bool valid = (i < N);
    int g = valid ? gid[i] : -1;           // input array, independent
    cudaGridDependencySynchronize();       // wait: k_scatter2 complete
    float u = 0.0f;
    if (valid) {
        unsigned long long p = __ldg(&g_node[i].deg);
        u = g_A[i] * rsqrtf(fmaxf((float)(unsigned)p, 1.0f));
    }
    int  g0  = __shfl_sync(0xffffffffu, g, 0);
    bool uni = __all_sync(0xffffffffu, valid && (g == g0));
    if (uni) {
#pragma unroll
        for (int o = 16; o > 0; o >>= 1)
            u += __shfl_xor_sync(0xffffffffu, u, o);
        if ((threadIdx.x & 31) == 0) {
            red_f32(&g_S[g0], u);
            red_f32(&g_cnt[g0], 32.0f);
        }
    } else if (valid) {
        red_f32(&g_S[g], u);
        red_f32(&g_cnt[g], 1.0f);
    }
}

// ---------------------------------------------------------------------------
// K5: out[g][c] = (S_g/max(cnt_g,1)) * rW_c.  rw GEMV before sync (inputs only).
// ---------------------------------------------------------------------------
__global__ void k_final(const float* __restrict__ W1, const float* __restrict__ W2,
                        const float* __restrict__ Wlast, float* __restrict__ out, int G) {
    int t = blockIdx.x * blockDim.x + threadIdx.x;
    int c = t & 7;
    float rw = 0.0f;
#pragma unroll
    for (int k = 0; k < 8; ++k) {
        float q = 0.0f;
#pragma unroll
        for (int j = 0; j < 8; ++j)
            q += fmaxf(__ldg(&W1[j]), 0.0f) * __ldg(&W2[j * 8 + k]);
        rw += fmaxf(q, 0.0f) * __ldg(&Wlast[k * 8 + c]);
    }
    cudaGridDependencySynchronize();       // wait: k_pool complete
    if (t >= G * 8) return;
    int g = t >> 3;
    out[t] = (g_S[g] / fmaxf(g_cnt[g], 1.0f)) * rw;
}

// ---------------------------------------------------------------------------
// kernel_launch — 6 nodes: 1 memset + 5 PDL-chained kernels (k_t eliminated).
// Inputs (metadata order): W1[8], W2[64], Wlast[64], src[E], dst[E], graph_ids[N]
// Output: G*C float32
// ---------------------------------------------------------------------------
extern "C" void kernel_launch(void* const* d_in, const int* in_sizes, int n_in,
                              void* d_out, int out_size) {
    const float* W1    = (const float*)d_in[0];
    const float* W2    = (const float*)d_in[1];
    const float* Wlast = (const float*)d_in[2];
    const int*   src   = (const int*)d_in[3];
    const int*   dst   = (const int*)d_in[4];
    const int*   gid   = (const int*)d_in[5];

    int E = in_sizes[3];
    int N = in_sizes[5];
    int G = out_size / 8;
    float* out = (float*)d_out;

    void* pnode;
    cudaGetSymbolAddress(&pnode, g_node);
    cudaMemsetAsync(pnode, 0, (size_t)N * sizeof(Node));   // deg + agg1, one node

    const int TB = 256;
    int nE8 = (E + 7) / 8;
    int nE4 = (E + 3) / 4;
    unsigned gE8 = (unsigned)((nE8 + TB - 1) / TB);
    unsigned gE4 = (unsigned)((nE4 + TB - 1) / TB);
    unsigned gN  = (unsigned)((N + TB - 1) / TB);
    unsigned gF  = (unsigned)((G * 8 + TB - 1) / TB);

    cudaLaunchAttribute attr[1];
    attr[0].id = cudaLaunchAttributeProgrammaticStreamSerialization;
    attr[0].val.programmaticStreamSerializationAllowed = 1;

    cudaLaunchConfig_t cfg{};
    cfg.blockDim = {TB, 1, 1};
    cfg.attrs = attr;
    cfg.numAttrs = 1;
    cfg.stream = 0;

    cfg.gridDim = {gE8, 1, 1};
    cudaLaunchKernelEx(&cfg, k_deg, src, dst, E);
    cudaLaunchKernelEx(&cfg, k_scatter1, src, dst, E, N);
    cfg.gridDim = {gE4, 1, 1};
    cudaLaunchKernelEx(&cfg, k_scatter2, src, dst, E);
    cfg.gridDim = {gN, 1, 1};
    cudaLaunchKernelEx(&cfg, k_pool, gid, N);
    cfg.gridDim = {gF, 1, 1};
    cudaLaunchKernelEx(&cfg, k_final, W1, W2, Wlast, out, G);
}

// round 14
// speedup vs baseline: 1.1639x; 1.1639x over previous
#include <cuda_runtime.h>
#include <cstdint>

// Problem constants (fixed by the dataset)
#define NN 500000
#define GG 1000

// ---------------------------------------------------------------------------
// Scratch (separate device symbols — scatters compile to 32 regs / ~87% occ).
// g_deg[n]: lo32 = deg_in, hi32 = deg_out (packed u64).
// ---------------------------------------------------------------------------
__device__ unsigned long long g_deg [NN];
__device__ float              g_agg1[NN];   // layer-1 scalar aggregation
__device__ float              g_t   [NN];   // s * isi * iso (layer-2 propagand)
__device__ float              g_A   [NN];   // layer-2 scalar aggregation
__device__ float              g_S   [GG];   // pooled scalar sum per graph
__device__ float              g_cnt [GG];   // nodes per graph

#define ONE_IN  1ull
#define ONE_OUT (1ull << 32)

__device__ __forceinline__ void red_f32(float* p, float v) {
    asm volatile("red.global.add.f32 [%0], %1;" :: "l"(p), "f"(v) : "memory");
}
__device__ __forceinline__ void red_u64(unsigned long long* p, unsigned long long v) {
    asm volatile("red.global.add.u64 [%0], %1;" :: "l"(p), "l"(v) : "memory");
}

// ---------------------------------------------------------------------------
// K1: degree counting, packed u64. 8 edges / thread, flat one-chunk-per-thread.
//     PDL: index loads (input-only) before the dependency sync (memset).
// ---------------------------------------------------------------------------
__global__ void k_deg(const int* __restrict__ src, const int* __restrict__ dst, int E) {
    int i = blockIdx.x * blockDim.x + threadIdx.x;
    int base = i << 3;
    if (base + 7 < E) {
        int4 s0 = *reinterpret_cast<const int4*>(src + base);
        int4 s1 = *reinterpret_cast<const int4*>(src + base + 4);
        int4 d0 = *reinterpret_cast<const int4*>(dst + base);
        int4 d1 = *reinterpret_cast<const int4*>(dst + base + 4);
        cudaGridDependencySynchronize();   // wait: g_deg memset visible
        red_u64(&g_deg[s0.x], ONE_OUT); red_u64(&g_deg[s0.y], ONE_OUT);
        red_u64(&g_deg[s0.z], ONE_OUT); red_u64(&g_deg[s0.w], ONE_OUT);
        red_u64(&g_deg[s1.x], ONE_OUT); red_u64(&g_deg[s1.y], ONE_OUT);
        red_u64(&g_deg[s1.z], ONE_OUT); red_u64(&g_deg[s1.w], ONE_OUT);
        red_u64(&g_deg[d0.x], ONE_IN);  red_u64(&g_deg[d0.y], ONE_IN);
        red_u64(&g_deg[d0.z], ONE_IN);  red_u64(&g_deg[d0.w], ONE_IN);
        red_u64(&g_deg[d1.x], ONE_IN);  red_u64(&g_deg[d1.y], ONE_IN);
        red_u64(&g_deg[d1.z], ONE_IN);  red_u64(&g_deg[d1.w], ONE_IN);
    } else {
        cudaGridDependencySynchronize();
        for (int e = base; e < E; ++e) {
            red_u64(&g_deg[src[e]], ONE_OUT);
            red_u64(&g_deg[dst[e]], ONE_IN);
        }
    }
}

// ---------------------------------------------------------------------------
// K2: layer-1 scatter, x0 inline. 8 edges / thread.
// ---------------------------------------------------------------------------
__device__ __forceinline__ float x0_of(unsigned long long p) {
    float di = (float)(unsigned)p;
    float dq = (float)(unsigned)(p >> 32);
    return di * rsqrtf(fmaxf(dq, 1.0f));
}

__global__ void k_scatter1(const int* __restrict__ src, const int* __restrict__ dst, int E) {
    int i = blockIdx.x * blockDim.x + threadIdx.x;
    int base = i << 3;
    if (base + 7 < E) {
        int4 s0 = *reinterpret_cast<const int4*>(src + base);
        int4 s1 = *reinterpret_cast<const int4*>(src + base + 4);
        int4 d0 = *reinterpret_cast<const int4*>(dst + base);
        int4 d1 = *reinterpret_cast<const int4*>(dst + base + 4);
        cudaGridDependencySynchronize();   // wait: k_deg complete
        float v0 = x0_of(__ldg(&g_deg[s0.x]));
        float v1 = x0_of(__ldg(&g_deg[s0.y]));
        float v2 = x0_of(__ldg(&g_deg[s0.z]));
        float v3 = x0_of(__ldg(&g_deg[s0.w]));
        float v4 = x0_of(__ldg(&g_deg[s1.x]));
        float v5 = x0_of(__ldg(&g_deg[s1.y]));
        float v6 = x0_of(__ldg(&g_deg[s1.z]));
        float v7 = x0_of(__ldg(&g_deg[s1.w]));
        red_f32(&g_agg1[d0.x], v0); red_f32(&g_agg1[d0.y], v1);
        red_f32(&g_agg1[d0.z], v2); red_f32(&g_agg1[d0.w], v3);
        red_f32(&g_agg1[d1.x], v4); red_f32(&g_agg1[d1.y], v5);
        red_f32(&g_agg1[d1.z], v6); red_f32(&g_agg1[d1.w], v7);
    } else {
        cudaGridDependencySynchronize();
        for (int e = base; e < E; ++e)
            red_f32(&g_agg1[dst[e]], x0_of(__ldg(&g_deg[src[e]])));
    }
}

// ---------------------------------------------------------------------------
// K3: t = agg1 * isi * iso — vectorized 4 nodes/thread.
//     Zeroes A/S/cnt BEFORE the dependency sync (independent of upstream).
// ---------------------------------------------------------------------------
__global__ void k_t(int N) {
    int i = blockIdx.x * blockDim.x + threadIdx.x;
    int base = i << 2;
    if (i < GG) { g_S[i] = 0.0f; g_cnt[i] = 0.0f; }       // untouched upstream
    if (base + 3 < N) {                                   // untouched upstream
        *reinterpret_cast<float4*>(g_A + base) = make_float4(0.f, 0.f, 0.f, 0.f);
    } else {
        for (int n = base; n < N; ++n) g_A[n] = 0.0f;
    }
    cudaGridDependencySynchronize();                      // wait: k_scatter1 done
    if (base + 3 < N) {
        ulonglong2 p01 = *reinterpret_cast<const ulonglong2*>(g_deg + base);
        ulonglong2 p23 = *reinterpret_cast<const ulonglong2*>(g_deg + base + 2);
        float4 a = *reinterpret_cast<const float4*>(g_agg1 + base);
        float4 r;
        r.x = a.x * rsqrtf(fmaxf((float)(unsigned)p01.x, 1.0f)) * rsqrtf(fmaxf((float)(unsigned)(p01.x >> 32), 1.0f));
        r.y = a.y * rsqrtf(fmaxf((float)(unsigned)p01.y, 1.0f)) * rsqrtf(fmaxf((float)(unsigned)(p01.y >> 32), 1.0f));
        r.z = a.z * rsqrtf(fmaxf((float)(unsigned)p23.x, 1.0f)) * rsqrtf(fmaxf((float)(unsigned)(p23.x >> 32), 1.0f));
        r.w = a.w * rsqrtf(fmaxf((float)(unsigned)p23.y, 1.0f)) * rsqrtf(fmaxf((float)(unsigned)(p23.y >> 32), 1.0f));
        *reinterpret_cast<float4*>(g_t + base) = r;
    } else {
        for (int n = base; n < N; ++n) {
            unsigned long long p = g_deg[n];
            g_t[n] = g_agg1[n]
                   * rsqrtf(fmaxf((float)(unsigned)p, 1.0f))
                   * rsqrtf(fmaxf((float)(unsigned)(p >> 32), 1.0f));
        }
    }
}

// ---------------------------------------------------------------------------
// K4: layer-2 scalar scatter  A[dst] += t[src]. 8 edges / thread.
// ---------------------------------------------------------------------------
__global__ void k_scatter2(const int* __restrict__ src, const int* __restrict__ dst, int E) {
    int i = blockIdx.x * blockDim.x + threadIdx.x;
    int base = i << 3;
    if (base + 7 < E) {
        int4 s0 = *reinterpret_cast<const int4*>(src + base);
        int4 s1 = *reinterpret_cast<const int4*>(src + base + 4);
        int4 d0 = *reinterpret_cast<const int4*>(dst + base);
        int4 d1 = *reinterpret_cast<const int4*>(dst + base + 4);
        cudaGridDependencySynchronize();   // wait: k_t complete (t and A=0)
        float v0 = __ldg(&g_t[s0.x]);
        float v1 = __ldg(&g_t[s0.y]);
        float v2 = __ldg(&g_t[s0.z]);
        float v3 = __ldg(&g_t[s0.w]);
        float v4 = __ldg(&g_t[s1.x]);
        float v5 = __ldg(&g_t[s1.y]);
        float v6 = __ldg(&g_t[s1.z]);
        float v7 = __ldg(&g_t[s1.w]);
        red_f32(&g_A[d0.x], v0); red_f32(&g_A[d0.y], v1);
        red_f32(&g_A[d0.z], v2); red_f32(&g_A[d0.w], v3);
        red_f32(&g_A[d1.x], v4); red_f32(&g_A[d1.y], v5);
        red_f32(&g_A[d1.z], v6); red_f32(&g_A[d1.w], v7);
    } else {
        cudaGridDependencySynchronize();
        for (int e = base; e < E; ++e)
            red_f32(&g_A[dst[e]], __ldg(&g_t[src[e]]));
    }
}

// ---------------------------------------------------------------------------
// K5: pooling. gid load (input) before sync; A/deg reads + REDs after.
// ---------------------------------------------------------------------------
__global__ void k_pool(const int* __restrict__ gid, int N) {
    int i = blockIdx.x * blockDim.x + threadIdx.x;
    bool valid = (i < N);
    int g = valid ? gid[i] : -1;           // input array, independent
    cudaGridDependencySynchronize();       // wait: k_scatter2 complete
    float u = 0.0f;
    if (valid) {
        unsigned long long p = g_deg[i];
        u = g_A[i] * rsqrtf(fmaxf((float)(unsigned)p, 1.0f));
    }
    int  g0  = __shfl_sync(0xffffffffu, g, 0);
    bool uni = __all_sync(0xffffffffu, valid && (g == g0));
    if (uni) {
#pragma unroll
        for (int o = 16; o > 0; o >>= 1)
            u += __shfl_xor_sync(0xffffffffu, u, o);
        if ((threadIdx.x & 31) == 0) {
            red_f32(&g_S[g0], u);
            red_f32(&g_cnt[g0], 32.0f);
        }
    } else if (valid) {
        red_f32(&g_S[g], u);
        red_f32(&g_cnt[g], 1.0f);
    }
}

// ---------------------------------------------------------------------------
// K6: out[g][c] = (S_g/max(cnt_g,1)) * rW_c.  rw GEMV before sync (inputs only).
// ---------------------------------------------------------------------------
__global__ void k_final(const float* __restrict__ W1, const float* __restrict__ W2,
                        const float* __restrict__ Wlast, float* __restrict__ out, int G) {
    int t = blockIdx.x * blockDim.x + threadIdx.x;
    int c = t & 7;
    float rw = 0.0f;
#pragma unroll
    for (int k = 0; k < 8; ++k) {
        float q = 0.0f;
#pragma unroll
        for (int j = 0; j < 8; ++j)
            q += fmaxf(__ldg(&W1[j]), 0.0f) * __ldg(&W2[j * 8 + k]);
        rw += fmaxf(q, 0.0f) * __ldg(&Wlast[k * 8 + c]);
    }
    cudaGridDependencySynchronize();       // wait: k_pool complete
    if (t >= G * 8) return;
    int g = t >> 3;
    out[t] = (g_S[g] / fmaxf(g_cnt[g], 1.0f)) * rw;
}

// ---------------------------------------------------------------------------
// kernel_launch — proven-best PDL chain (TB=256, flat oversubscribed grids,
// implicit PDL triggers, dense scalar scratch arrays). Final configuration.
// Inputs (metadata order): W1[8], W2[64], Wlast[64], src[E], dst[E], graph_ids[N]
// Output: G*C float32
// ---------------------------------------------------------------------------
extern "C" void kernel_launch(void* const* d_in, const int* in_sizes, int n_in,
                              void* d_out, int out_size) {
    const float* W1    = (const float*)d_in[0];
    const float* W2    = (const float*)d_in[1];
    const float* Wlast = (const float*)d_in[2];
    const int*   src   = (const int*)d_in[3];
    const int*   dst   = (const int*)d_in[4];
    const int*   gid   = (const int*)d_in[5];

    int E = in_sizes[3];
    int N = in_sizes[5];
    int G = out_size / 8;
    float* out = (float*)d_out;

    void *pdeg, *pa1;
    cudaGetSymbolAddress(&pdeg, g_deg);
    cudaGetSymbolAddress(&pa1,  g_agg1);
    cudaMemsetAsync(pdeg, 0, (size_t)N * sizeof(unsigned long long));
    cudaMemsetAsync(pa1,  0, (size_t)N * sizeof(float));

    const int TB = 256;
    int nE8 = (E + 7) / 8;
    unsigned gE8 = (unsigned)((nE8 + TB - 1) / TB);
    unsigned gN  = (unsigned)((N + TB - 1) / TB);
    unsigned gN4 = (unsigned)(((N + 3) / 4 + TB - 1) / TB);
    unsigned gF  = (unsigned)((G * 8 + TB - 1) / TB);

    cudaLaunchAttribute attr[1];
    attr[0].id = cudaLaunchAttributeProgrammaticStreamSerialization;
    attr[0].val.programmaticStreamSerializationAllowed = 1;

    cudaLaunchConfig_t cfg{};
    cfg.blockDim = {TB, 1, 1};
    cfg.attrs = attr;
    cfg.numAttrs = 1;
    cfg.stream = 0;

    cfg.gridDim = {gE8, 1, 1};
    cudaLaunchKernelEx(&cfg, k_deg, src, dst, E);
    cudaLaunchKernelEx(&cfg, k_scatter1, src, dst, E);
    cfg.gridDim = {gN4, 1, 1};
    cudaLaunchKernelEx(&cfg, k_t, N);
    cfg.gridDim = {gE8, 1, 1};
    cudaLaunchKernelEx(&cfg, k_scatter2, src, dst, E);
    cfg.gridDim = {gN, 1, 1};
    cudaLaunchKernelEx(&cfg, k_pool, gid, N);
    cfg.gridDim = {gF, 1, 1};
    cudaLaunchKernelEx(&cfg, k_final, W1, W2, Wlast, out, G);
}